// round 16
// baseline (speedup 1.0000x reference)
#include <cuda_runtime.h>
#include <cuda_bf16.h>
#include <cstdint>

#define NT 2000
#define NS 512
#define NH 64
#define NSNH (NS * NH)

// Output packing (concatenated flattened tuple, float32):
//   Q  : [NT, NS]        at 0
//   C  : [NT, NS]        at 1,024,000
//   S  : [NT, NS, NH]    at 2,048,000
//   H1 : [NT, NS, NH]    at 67,584,000
//   H2 : [NT, NS, NH]    at 133,120,000
//   Qs : [NT, NS, 3]     at 198,656,000
#define OFF_C   1024000
#define OFF_S   2048000
#define OFF_H1  67584000
#define OFF_H2  133120000
#define OFF_QS  198656000

#define CH 16            // steps per chunk; 2000 = 125 * 16 exactly
#define NCHUNK 125

__device__ __forceinline__ float sigmoidf(float x) {
    return 1.0f / (1.0f + expf(-x));
}

// 256B smem -> gmem async bulk store (TMA engine, bypasses STG/L1tex path)
__device__ __forceinline__ void bulk_store_256(float* gdst, uint32_t ssrc) {
    asm volatile("cp.async.bulk.global.shared::cta.bulk_group [%0], [%1], 256;"
                 :: "l"(gdst), "r"(ssrc) : "memory");
}
__device__ __forceinline__ void bulk_commit() {
    asm volatile("cp.async.bulk.commit_group;" ::: "memory");
}
template <int N>
__device__ __forceinline__ void bulk_wait_read() {
    asm volatile("cp.async.bulk.wait_group.read %0;" :: "n"(N) : "memory");
}
__device__ __forceinline__ void fence_async_shared() {
    asm volatile("fence.proxy.async.shared::cta;" ::: "memory");
}

__global__ void __launch_bounds__(32, 6)
soil_cq_kernel(const float* __restrict__ P, const float* __restrict__ T,
               const float* __restrict__ E,
               const float* __restrict__ w,  const float* __restrict__ wk1,
               const float* __restrict__ wk2, const float* __restrict__ we1,
               const float* __restrict__ we2, const float* __restrict__ wl,
               const float* __restrict__ wo,  const float* __restrict__ wc,
               float* __restrict__ out)
{
    const int lane = threadIdx.x;           // 0..31
    const int site = blockIdx.x;            // 0..511
    const int j0 = lane * 2;
    const int j1 = j0 + 1;

    // double-buffered state staging: [buf][array][step][unit] (24 KB)
    __shared__ __align__(128) float stg[2][3][CH][NH];
    // [step][lane] packed partials; padded to 33 for conflict-free
    // transposed LDS.128 in phase 2 (8.4 KB)
    __shared__ float4 pbuf[CH][33];
    __shared__ float4 fbuf[2][CH];          // forcing chunks (p,t,e,_)

    // ---- per-thread parameter precompute (2 hidden units per lane) ----
    const float ew0 = expf(w[j0]) + 1.0f,  ew1 = expf(w[j1]) + 1.0f;
    const float sk10 = sigmoidf(wk1[j0]),  sk11 = sigmoidf(wk1[j1]);
    const float sk20 = sigmoidf(wk2[j0]),  sk21 = sigmoidf(wk2[j1]);
    const float se10 = sigmoidf(we1[j0]),  se11 = sigmoidf(we1[j1]);
    const float se20 = sigmoidf(we2[j0]),  se21 = sigmoidf(we2[j1]);
    const float L0   = expf(wl[j0]),       L1   = expf(wl[j1]);
    const float csk10 = 1.0f - sk10,        csk11 = 1.0f - sk11;
    const float csk20 = 1.0f - 2.0f * sk20, csk21 = 1.0f - 2.0f * sk21;

    // softmax(wo) across the warp's 64 units
    float ex0 = expf(wo[j0]), ex1 = expf(wo[j1]);
    float esum = ex0 + ex1;
    #pragma unroll
    for (int o = 16; o; o >>= 1) esum += __shfl_xor_sync(0xffffffffu, esum, o);
    const float a0 = ex0 / esum, a1 = ex1 / esum;
    const float ar0 = a0 / (sk20 * (1.0f + expf(wc[j0])));
    const float ar1 = a1 / (sk21 * (1.0f + expf(wc[j1])));

    // folded output coefficients: q1*a = h1a*(sk1*a), etc.
    const float ska10 = sk10 * a0,  ska11 = sk11 * a1;
    const float ska20 = sk20 * a0,  ska21 = sk21 * a1;
    const float skr20 = sk20 * ar0, skr21 = sk21 * ar1;

    // ---- state in registers ----
    float s0 = 0.f, s1 = 0.f, h10 = 0.f, h11 = 0.f, h20 = 0.f, h21 = 0.f;

    // ---- stage chunk-0 forcings ----
    if (lane < CH) {
        fbuf[0][lane] = make_float4(P[lane * NS + site],
                                    T[lane * NS + site],
                                    E[lane * NS + site], 0.f);
    }
    __syncwarp();

    const uint32_t stg_base =
        (uint32_t)__cvta_generic_to_shared(&stg[0][0][0][0]);

    #pragma unroll 1
    for (int c = 0; c < NCHUNK; ++c) {
        const int buf = c & 1;
        const int t0  = c * CH;

        // prefetch next chunk's forcings into registers (hidden under phase 1)
        float pN = 0.f, tN = 0.f, eN = 0.f;
        if (lane < CH) {
            const int tn = t0 + CH + lane;
            if (tn < NT) {
                pN = P[tn * NS + site];
                tN = T[tn * NS + site];
                eN = E[tn * NS + site];
            }
        }

        // buffer `buf` was consumed by the bulk group committed in chunk c-2;
        // allow at most 1 pending group (c-1's) before overwriting it.
        bulk_wait_read<1>();
        __syncwarp();

        // ================= phase 1: recurrence, STS-only stores =================
        #pragma unroll
        for (int i = 0; i < CH; ++i) {
            const float4 f = fbuf[buf][i];
            const float p = f.x, t = f.y, e = f.z;

            const float trel = fmaxf(t, 0.0f);
            const float ppos = (t > 0.0f) ? p : 0.0f;
            const float pneg = (t < 0.0f) ? p : 0.0f;

            // ---- unit 0 ----
            const float m0   = fminf(trel * ew0, s0);
            s0 = s0 - m0 + pneg;
            const float x0   = ppos + m0;
            const float h2x0 = h20 + x0;
            const float h1a0 = fmaxf(h10 + h2x0 - L0, 0.0f);
            const float h2a0 = fminf(h1a0 + h2x0, L0);
            h10 = fmaxf(fmaf(h1a0, csk10, -e * se10), 0.0f);
            h20 = fmaxf(fmaf(h2a0, csk20, -e * se20), 0.0f);

            // ---- unit 1 ----
            const float m1   = fminf(trel * ew1, s1);
            s1 = s1 - m1 + pneg;
            const float x1   = ppos + m1;
            const float h2x1 = h21 + x1;
            const float h1a1 = fmaxf(h11 + h2x1 - L1, 0.0f);
            const float h2a1 = fminf(h1a1 + h2x1, L1);
            h11 = fmaxf(fmaf(h1a1, csk11, -e * se11), 0.0f);
            h21 = fmaxf(fmaf(h2a1, csk21, -e * se21), 0.0f);

            // ---- state to smem staging (3x STS.64, conflict-free rows) ----
            *(float2*)&stg[buf][0][i][j0] = make_float2(s0,  s1);
            *(float2*)&stg[buf][1][i][j0] = make_float2(h10, h11);
            *(float2*)&stg[buf][2][i][j0] = make_float2(h20, h21);

            // ---- packed per-lane partials: one STS.128 ----
            pbuf[i][lane] = make_float4(fmaf(h1a1, ska11, h1a0 * ska10),
                                        fmaf(h2a1, ska21, h2a0 * ska20),
                                        fmaf(h2a1, skr21, h2a0 * skr20),
                                        0.0f);
        }

        // stage next chunk's forcings
        if (lane < CH) fbuf[buf ^ 1][lane] = make_float4(pN, tN, eN, 0.f);

        __syncwarp();            // staging + pbuf complete
        fence_async_shared();    // order STS (generic proxy) before TMA reads

        // ---- async bulk stores: lane i ships step t0+i (3 x 256B) ----
        if (lane < CH) {
            const size_t tt = (size_t)(t0 + lane) * NSNH + (size_t)site * NH;
            const uint32_t src = stg_base
                               + (uint32_t)buf * (3 * CH * NH * 4)
                               + (uint32_t)lane * (NH * 4);
            bulk_store_256(out + OFF_S  + tt, src);
            bulk_store_256(out + OFF_H1 + tt, src + CH * NH * 4);
            bulk_store_256(out + OFF_H2 + tt, src + 2 * CH * NH * 4);
            bulk_commit();
        }

        // ====== phase 2: lane i reduces + emits outputs of step t0+i ======
        if (lane < CH) {
            const float4* row = pbuf[lane];
            float x0 = 0.f, x1 = 0.f, x2 = 0.f, x3 = 0.f;
            float y0 = 0.f, y1 = 0.f, y2 = 0.f, y3 = 0.f;
            float z0 = 0.f, z1 = 0.f, z2 = 0.f, z3 = 0.f;
            #pragma unroll
            for (int k = 0; k < 32; k += 4) {
                const float4 v0 = row[k],     v1 = row[k + 1];
                const float4 v2 = row[k + 2], v3 = row[k + 3];
                x0 += v0.x; x1 += v1.x; x2 += v2.x; x3 += v3.x;
                y0 += v0.y; y1 += v1.y; y2 += v2.y; y3 += v3.y;
                z0 += v0.z; z1 += v1.z; z2 += v2.z; z3 += v3.z;
            }
            const float Qs1 = (x0 + x1) + (x2 + x3);
            const float Qs2 = (y0 + y1) + (y2 + y3);
            const float qcS = (z0 + z1) + (z2 + z3);
            const float Qk  = Qs1 + Qs2;
            const float cc  = __fdividef(qcS * (1.0f / 64.0f) + 1e-5f, Qk + 1e-5f);

            const int t = t0 + lane;
            out[t * NS + site]         = Qk;
            out[OFF_C + t * NS + site] = cc;
            float* qs = out + OFF_QS + ((size_t)t * NS + site) * 3;
            qs[0] = Qs1;
            qs[1] = Qs2;
            qs[2] = 0.0f;
        }
    }

    // drain all pending bulk stores before exit
    bulk_wait_read<0>();
}

extern "C" void kernel_launch(void* const* d_in, const int* in_sizes, int n_in,
                              void* d_out, int out_size)
{
    (void)in_sizes; (void)n_in; (void)out_size;
    soil_cq_kernel<<<NS, 32>>>(
        (const float*)d_in[0], (const float*)d_in[1], (const float*)d_in[2],
        (const float*)d_in[3], (const float*)d_in[4], (const float*)d_in[5],
        (const float*)d_in[6], (const float*)d_in[7], (const float*)d_in[8],
        (const float*)d_in[9], (const float*)d_in[10],
        (float*)d_out);
}

// round 17
// speedup vs baseline: 1.9172x; 1.9172x over previous
#include <cuda_runtime.h>
#include <cuda_bf16.h>

#define NT 2000
#define NS 512
#define NH 64
#define NSNH (NS * NH)

// Output packing (concatenated flattened tuple, float32):
//   Q  : [NT, NS]        at 0
//   C  : [NT, NS]        at 1,024,000
//   S  : [NT, NS, NH]    at 2,048,000
//   H1 : [NT, NS, NH]    at 67,584,000
//   H2 : [NT, NS, NH]    at 133,120,000
//   Qs : [NT, NS, 3]     at 198,656,000
#define OFF_C   1024000
#define OFF_S   2048000
#define OFF_H1  67584000
#define OFF_H2  133120000
#define OFF_QS  198656000

// 2-segment asymmetric split balanced for full:warm instr ratio ~50:22.
// seg0 emits chunks [0,40); seg1 warm-replays [0,40) then emits [40,63).
#define SPLIT_CHUNK 40

__device__ __forceinline__ float sigmoidf(float x) {
    return 1.0f / (1.0f + expf(-x));
}

__global__ void __launch_bounds__(32, 16)
soil_cq_kernel(const float* __restrict__ P, const float* __restrict__ T,
               const float* __restrict__ E,
               const float* __restrict__ w,  const float* __restrict__ wk1,
               const float* __restrict__ wk2, const float* __restrict__ we1,
               const float* __restrict__ we2, const float* __restrict__ wl,
               const float* __restrict__ wo,  const float* __restrict__ wc,
               float* __restrict__ out)
{
    const int lane = threadIdx.x;             // 0..31
    const int site = blockIdx.x >> 1;         // 0..511
    const int seg  = blockIdx.x & 1;          // time segment 0..1
    const int c_start = seg ? SPLIT_CHUNK : 0;
    const int c_end   = seg ? 63 : SPLIT_CHUNK;
    const int j0 = lane * 2;
    const int j1 = j0 + 1;

    // [step][lane] packed partials (q1a, q2a, qc, 0); padded to 33 for
    // conflict-free transposed LDS.128 in phase 2
    __shared__ float4 pbuf[32][33];
    __shared__ float4 fbuf[2][32];            // forcing chunks (p,t,e,_)

    // ---- per-thread parameter precompute (2 hidden units per lane) ----
    const float ew0 = expf(w[j0]) + 1.0f,  ew1 = expf(w[j1]) + 1.0f;
    const float sk10 = sigmoidf(wk1[j0]),  sk11 = sigmoidf(wk1[j1]);
    const float sk20 = sigmoidf(wk2[j0]),  sk21 = sigmoidf(wk2[j1]);
    const float se10 = sigmoidf(we1[j0]),  se11 = sigmoidf(we1[j1]);
    const float se20 = sigmoidf(we2[j0]),  se21 = sigmoidf(we2[j1]);
    const float L0   = expf(wl[j0]),       L1   = expf(wl[j1]);
    const float csk10 = 1.0f - sk10,        csk11 = 1.0f - sk11;
    const float csk20 = 1.0f - 2.0f * sk20, csk21 = 1.0f - 2.0f * sk21;

    // softmax(wo) across the warp's 64 units
    float ex0 = expf(wo[j0]), ex1 = expf(wo[j1]);
    float esum = ex0 + ex1;
    #pragma unroll
    for (int o = 16; o; o >>= 1) esum += __shfl_xor_sync(0xffffffffu, esum, o);
    const float a0 = ex0 / esum, a1 = ex1 / esum;
    const float ar0 = a0 / (sk20 * (1.0f + expf(wc[j0])));
    const float ar1 = a1 / (sk21 * (1.0f + expf(wc[j1])));

    // folded output coefficients: q1*a = h1a*(sk1*a), etc.
    const float ska10 = sk10 * a0,  ska11 = sk11 * a1;
    const float ska20 = sk20 * a0,  ska21 = sk21 * a1;
    const float skr20 = sk20 * ar0, skr21 = sk21 * ar1;

    // ---- state in registers ----
    float s0 = 0.f, s1 = 0.f, h10 = 0.f, h11 = 0.f, h20 = 0.f, h21 = 0.f;

    // ---- state output pointers, positioned at this segment's first full step ----
    float* Sp  = out + OFF_S  + (size_t)site * NH + j0
                     + (size_t)c_start * 32 * NSNH;
    float* H1p = out + OFF_H1 + (size_t)site * NH + j0
                     + (size_t)c_start * 32 * NSNH;
    float* H2p = out + OFF_H2 + (size_t)site * NH + j0
                     + (size_t)c_start * 32 * NSNH;

    // ---- stage chunk-0 forcings ----
    fbuf[0][lane] = make_float4(P[lane * NS + site],
                                T[lane * NS + site],
                                E[lane * NS + site], 0.f);

    #pragma unroll 1
    for (int c = 0; c < c_end; ++c) {
        const int buf = c & 1;
        const int t0  = c * 32;
        const int rem = (c == 62) ? 16 : 32;

        // prefetch next chunk's forcings into registers (hidden under phase 1)
        float pN = 0.f, tN = 0.f, eN = 0.f;
        {
            const int tn = t0 + 32 + lane;
            if (tn < NT) {
                pN = P[tn * NS + site];
                tN = T[tn * NS + site];
                eN = E[tn * NS + site];
            }
        }

        __syncwarp();   // fbuf[buf] staged; prev phase-2 done reading pbuf

        if (c < c_start) {
            // ===== warm-up: recurrence only (bitwise-identical, no stores) =====
            #pragma unroll 8
            for (int i = 0; i < 32; ++i) {
                const float4 f = fbuf[buf][i];
                const float p = f.x, t = f.y, e = f.z;

                const float trel = fmaxf(t, 0.0f);
                const float ppos = (t > 0.0f) ? p : 0.0f;
                const float pneg = (t < 0.0f) ? p : 0.0f;

                const float m0   = fminf(trel * ew0, s0);
                s0 = s0 - m0 + pneg;
                const float x0   = ppos + m0;
                const float h2x0 = h20 + x0;
                const float h1a0 = fmaxf(h10 + h2x0 - L0, 0.0f);
                const float h2a0 = fminf(h1a0 + h2x0, L0);
                h10 = fmaxf(fmaf(h1a0, csk10, -e * se10), 0.0f);
                h20 = fmaxf(fmaf(h2a0, csk20, -e * se20), 0.0f);

                const float m1   = fminf(trel * ew1, s1);
                s1 = s1 - m1 + pneg;
                const float x1   = ppos + m1;
                const float h2x1 = h21 + x1;
                const float h1a1 = fmaxf(h11 + h2x1 - L1, 0.0f);
                const float h2a1 = fminf(h1a1 + h2x1, L1);
                h11 = fmaxf(fmaf(h1a1, csk11, -e * se11), 0.0f);
                h21 = fmaxf(fmaf(h2a1, csk21, -e * se21), 0.0f);
            }
        } else {
            // ================= full: recurrence + outputs =================
            #pragma unroll 8
            for (int i = 0; i < rem; ++i) {
                const float4 f = fbuf[buf][i];
                const float p = f.x, t = f.y, e = f.z;

                const float trel = fmaxf(t, 0.0f);
                const float ppos = (t > 0.0f) ? p : 0.0f;
                const float pneg = (t < 0.0f) ? p : 0.0f;

                const float m0   = fminf(trel * ew0, s0);
                s0 = s0 - m0 + pneg;
                const float x0   = ppos + m0;
                const float h2x0 = h20 + x0;
                const float h1a0 = fmaxf(h10 + h2x0 - L0, 0.0f);
                const float h2a0 = fminf(h1a0 + h2x0, L0);
                h10 = fmaxf(fmaf(h1a0, csk10, -e * se10), 0.0f);
                h20 = fmaxf(fmaf(h2a0, csk20, -e * se20), 0.0f);

                const float m1   = fminf(trel * ew1, s1);
                s1 = s1 - m1 + pneg;
                const float x1   = ppos + m1;
                const float h2x1 = h21 + x1;
                const float h1a1 = fmaxf(h11 + h2x1 - L1, 0.0f);
                const float h2a1 = fminf(h1a1 + h2x1, L1);
                h11 = fmaxf(fmaf(h1a1, csk11, -e * se11), 0.0f);
                h21 = fmaxf(fmaf(h2a1, csk21, -e * se21), 0.0f);

                // coalesced state stores (256B/warp/array)
                *(float2*)Sp  = make_float2(s0,  s1);
                *(float2*)H1p = make_float2(h10, h11);
                *(float2*)H2p = make_float2(h20, h21);
                Sp  += NSNH;
                H1p += NSNH;
                H2p += NSNH;

                // packed per-lane partials: ONE STS.128
                pbuf[i][lane] = make_float4(fmaf(h1a1, ska11, h1a0 * ska10),
                                            fmaf(h2a1, ska21, h2a0 * ska20),
                                            fmaf(h2a1, skr21, h2a0 * skr20),
                                            0.0f);
            }
        }

        // stage next chunk's forcings
        fbuf[buf ^ 1][lane] = make_float4(pN, tN, eN, 0.f);

        __syncwarp();   // pbuf complete; fbuf[buf^1] staged

        // ===== phase 2 (full chunks only): lane i reduces step t0+i =====
        if (c >= c_start && lane < rem) {
            const float4* row = pbuf[lane];
            float x0 = 0.f, x1 = 0.f, x2 = 0.f, x3 = 0.f;
            float y0 = 0.f, y1 = 0.f, y2 = 0.f, y3 = 0.f;
            float z0 = 0.f, z1 = 0.f, z2 = 0.f, z3 = 0.f;
            #pragma unroll
            for (int k = 0; k < 32; k += 4) {
                const float4 v0 = row[k],     v1 = row[k + 1];
                const float4 v2 = row[k + 2], v3 = row[k + 3];
                x0 += v0.x; x1 += v1.x; x2 += v2.x; x3 += v3.x;
                y0 += v0.y; y1 += v1.y; y2 += v2.y; y3 += v3.y;
                z0 += v0.z; z1 += v1.z; z2 += v2.z; z3 += v3.z;
            }
            const float Qs1 = (x0 + x1) + (x2 + x3);
            const float Qs2 = (y0 + y1) + (y2 + y3);
            const float qcS = (z0 + z1) + (z2 + z3);
            const float Qk  = Qs1 + Qs2;
            const float cc  = __fdividef(qcS * (1.0f / 64.0f) + 1e-5f, Qk + 1e-5f);

            const int t = t0 + lane;
            out[t * NS + site]         = Qk;
            out[OFF_C + t * NS + site] = cc;
            float* qs = out + OFF_QS + ((size_t)t * NS + site) * 3;
            qs[0] = Qs1;
            qs[1] = Qs2;
            qs[2] = 0.0f;
        }
    }
}

extern "C" void kernel_launch(void* const* d_in, const int* in_sizes, int n_in,
                              void* d_out, int out_size)
{
    (void)in_sizes; (void)n_in; (void)out_size;
    soil_cq_kernel<<<NS * 2, 32>>>(
        (const float*)d_in[0], (const float*)d_in[1], (const float*)d_in[2],
        (const float*)d_in[3], (const float*)d_in[4], (const float*)d_in[5],
        (const float*)d_in[6], (const float*)d_in[7], (const float*)d_in[8],
        (const float*)d_in[9], (const float*)d_in[10],
        (float*)d_out);
}